// round 1
// baseline (speedup 1.0000x reference)
#include <cuda_runtime.h>
#include <math.h>

#define NB 8
#define NH 256
#define NW 256
#define NPIX (NB*NH*NW)
#define SENT 0x7FFF

// Scratch (static __device__ per allocation rules)
__device__ unsigned int g_col[NPIX];     // packed ushort (fg | bg<<16) vertical distances
__device__ float        g_absd[NPIX];    // |dist| = fgd + bgd
__device__ unsigned int g_fgmax[NB];
__device__ unsigned int g_bgmax[NB];
__device__ int          g_hasfg[NB];
__device__ float        g_part[NB*NH*12]; // per-row partials: [0:4) focal, [4:8) inter, [8:12) (p+t)*w

__global__ void k_zero() {
    int t = threadIdx.x;
    if (t < NB) { g_fgmax[t] = 0u; g_bgmax[t] = 0u; g_hasfg[t] = 0; }
}

// Vertical 1D distance per column (both feats), two sweeps. One thread per column.
__global__ void k_vert(const int* __restrict__ tg) {
    int b = blockIdx.x, j = threadIdx.x;
    const int* t = tg + b * NH * NW;
    unsigned int* gc = g_col + b * NH * NW;
    int lastf = -SENT, lastb = -SENT;
    bool anyb = false;
    #pragma unroll 4
    for (int h = 0; h < NH; ++h) {
        int m = t[h * NW + j];
        if (m) { lastb = h; anyb = true; } else { lastf = h; }
        int df = min(h - lastf, SENT);
        int db = min(h - lastb, SENT);
        gc[h * NW + j] = (unsigned)df | ((unsigned)db << 16);
    }
    int nextf = 2 * SENT, nextb = 2 * SENT;
    #pragma unroll 4
    for (int h = NH - 1; h >= 0; --h) {
        unsigned v = gc[h * NW + j];      // same-thread read-after-write: safe
        int df = (int)(v & 0xFFFFu);
        int db = (int)(v >> 16);
        if (df == 0) nextf = h;
        if (db == 0) nextb = h;
        df = min(df, min(nextf - h, SENT));
        db = min(db, min(nextb - h, SENT));
        gc[h * NW + j] = (unsigned)df | ((unsigned)db << 16);
    }
    unsigned bal = __ballot_sync(0xffffffffu, anyb);
    if ((j & 31) == 0 && bal) atomicOr(&g_hasfg[b], 1);
}

// Horizontal envelope with pruned outward scan (exact). One block per (b,h) row.
__global__ void k_edt() {
    int blk = blockIdx.x;
    int b = blk >> 8, h = blk & 255;
    int jo = threadIdx.x;
    __shared__ float sf[NW], sb[NW];
    unsigned v = g_col[(b * NH + h) * NW + jo];
    int df = (int)(v & 0xFFFFu), db = (int)(v >> 16);
    sf[jo] = (df >= SENT) ? 1e6f : (float)df;
    sb[jo] = (db >= SENT) ? 1e6f : (float)db;
    __syncthreads();
    float gf = sf[jo], gb = sb[jo];
    float bf = gf * gf;
    float bb = gb * gb;
    for (int r = 1; r < NW; ++r) {
        float c = (float)(r * r);
        if (c >= bf && c >= bb) break;
        int jl = jo - r, jr = jo + r;
        if (jl >= 0) {
            float a = sf[jl]; float x = sb[jl];
            float cf = a * a + c; float cb = x * x + c;
            bf = fminf(bf, cf); bb = fminf(bb, cb);
        }
        if (jr < NW) {
            float a = sf[jr]; float x = sb[jr];
            float cf = a * a + c; float cb = x * x + c;
            bf = fminf(bf, cf); bb = fminf(bb, cb);
        }
    }
    float fgd = sqrtf(bf);
    float bgd = sqrtf(bb);
    g_absd[(b * NH + h) * NW + jo] = fgd + bgd;   // exactly one of fgd/bgd is 0

    // block max (order-independent), then one atomicMax per block
    float mf = fgd, mb = bgd;
    #pragma unroll
    for (int o = 16; o; o >>= 1) {
        mf = fmaxf(mf, __shfl_down_sync(0xffffffffu, mf, o));
        mb = fmaxf(mb, __shfl_down_sync(0xffffffffu, mb, o));
    }
    __shared__ float smf[8], smb[8];
    int lane = jo & 31, wq = jo >> 5;
    if (lane == 0) { smf[wq] = mf; smb[wq] = mb; }
    __syncthreads();
    if (jo == 0) {
        #pragma unroll
        for (int q = 1; q < 8; ++q) { mf = fmaxf(mf, smf[q]); mb = fmaxf(mb, smb[q]); }
        atomicMax(&g_fgmax[b], __float_as_uint(mf));
        atomicMax(&g_bgmax[b], __float_as_uint(mb));
    }
}

__device__ __forceinline__ float softplusf(float z) {
    return (z > 0.f) ? (z + log1pf(expf(-z))) : log1pf(expf(z));
}

// Fused focal + IoU partials. One block per (b,h) row; 12 partial sums per block.
__global__ void k_loss(const float* __restrict__ p0, const float* __restrict__ p1,
                       const float* __restrict__ p2, const float* __restrict__ p3,
                       const int* __restrict__ tg) {
    int blk = blockIdx.x;
    int b = blk >> 8, h = blk & 255;
    int jo = threadIdx.x;
    int idx = (b * NH + h) * NW + jo;

    float mdf = __uint_as_float(g_fgmax[b]);
    float mdb = __uint_as_float(g_bgmax[b]);
    float md = fmaxf(mdf, mdb);
    float w;
    if (g_hasfg[b] && md > 0.f) {
        float safe3 = fmaxf(md, 1e-12f) / 3.0f;
        w = 1.f + expf(-g_absd[idx] / safe3);
    } else {
        w = 1.f;
    }

    int ti = tg[idx];
    float t = (float)ti;
    const float* ps[4] = { p0, p1, p2, p3 };
    float vals[12];
    #pragma unroll
    for (int k = 0; k < 4; ++k) {
        float x = ps[k][idx];
        float p = 1.f / (1.f + expf(-x));
        float ce, omp, al;
        if (ti) { ce = softplusf(-x); omp = 1.f - p; al = 0.25f; }
        else    { ce = softplusf(x);  omp = p;       al = 0.75f; }
        vals[k]     = al * omp * omp * ce;   // focal term
        vals[4 + k] = ti ? (p * w) : 0.f;    // inter
        vals[8 + k] = (p + t) * w;           // (p+t)*w
    }

    #pragma unroll
    for (int k = 0; k < 12; ++k) {
        #pragma unroll
        for (int o = 16; o; o >>= 1)
            vals[k] += __shfl_down_sync(0xffffffffu, vals[k], o);
    }
    __shared__ float sred[8][12];
    int lane = jo & 31, wq = jo >> 5;
    if (lane == 0) {
        #pragma unroll
        for (int k = 0; k < 12; ++k) sred[wq][k] = vals[k];
    }
    __syncthreads();
    if (jo < 12) {
        float s = 0.f;
        #pragma unroll
        for (int q = 0; q < 8; ++q) s += sred[q][jo];
        g_part[blk * 12 + jo] = s;
    }
}

// Final combine: deterministic fixed-order reductions.
__global__ void k_final(float* __restrict__ out) {
    int tid = threadIdx.x;           // 256 threads
    int lane = tid & 31, wq = tid >> 5;

    // IoU: warp wq handles batch wq (8 warps = 8 batches)
    __shared__ float s_iou[NB][4];
    {
        float in_[4] = {0.f,0.f,0.f,0.f}, u_[4] = {0.f,0.f,0.f,0.f};
        for (int r = lane; r < NH; r += 32) {
            const float* pp = g_part + (wq * NH + r) * 12;
            #pragma unroll
            for (int k = 0; k < 4; ++k) { in_[k] += pp[4 + k]; u_[k] += pp[8 + k]; }
        }
        #pragma unroll
        for (int k = 0; k < 4; ++k) {
            #pragma unroll
            for (int o = 16; o; o >>= 1) {
                in_[k] += __shfl_down_sync(0xffffffffu, in_[k], o);
                u_[k]  += __shfl_down_sync(0xffffffffu, u_[k],  o);
            }
        }
        if (lane == 0) {
            #pragma unroll
            for (int k = 0; k < 4; ++k) {
                float inter = in_[k];
                float un = u_[k] - inter;
                s_iou[wq][k] = (inter + 1e-6f) / (un + 1e-6f);
            }
        }
    }

    // Focal: tree reduce over 2048 row-partials
    float f[4] = {0.f,0.f,0.f,0.f};
    for (int i = tid; i < NB * NH; i += 256) {
        const float* pp = g_part + i * 12;
        #pragma unroll
        for (int k = 0; k < 4; ++k) f[k] += pp[k];
    }
    __shared__ float sf4[4][256];
    #pragma unroll
    for (int k = 0; k < 4; ++k) sf4[k][tid] = f[k];
    __syncthreads();
    for (int s = 128; s; s >>= 1) {
        if (tid < s) {
            #pragma unroll
            for (int k = 0; k < 4; ++k) sf4[k][tid] += sf4[k][tid + s];
        }
        __syncthreads();
    }

    if (tid == 0) {
        const float wgt[4] = { 1.0f, 0.4f, 0.2f, 0.4f / 3.0f };
        float total = 0.f;
        #pragma unroll
        for (int k = 0; k < 4; ++k) {
            float fm = sf4[k][0] / (float)NPIX;
            float is = 0.f;
            #pragma unroll
            for (int b2 = 0; b2 < NB; ++b2) is += s_iou[b2][k];
            float il = 1.f - is / (float)NB;
            total += wgt[k] * (fm + il);
        }
        out[0] = total;
    }
}

extern "C" void kernel_launch(void* const* d_in, const int* in_sizes, int n_in,
                              void* d_out, int out_size) {
    const float* p0 = (const float*)d_in[0];   // pred_main
    const float* p1 = (const float*)d_in[1];   // aux0
    const float* p2 = (const float*)d_in[2];   // aux1
    const float* p3 = (const float*)d_in[3];   // aux2
    const int*   tg = (const int*)d_in[4];     // targets

    k_zero <<<1, 32>>>();
    k_vert <<<NB, NW>>>(tg);
    k_edt  <<<NB * NH, NW>>>();
    k_loss <<<NB * NH, NW>>>(p0, p1, p2, p3, tg);
    k_final<<<1, 256>>>((float*)d_out);
}

// round 2
// speedup vs baseline: 3.1757x; 3.1757x over previous
#include <cuda_runtime.h>
#include <math.h>

#define NB 8
#define NH 256
#define NW 256
#define NPIX (NB*NH*NW)
#define NCH 8              // 8 chunks of 32 rows
#define BLKB 64            // k_loss blocks per batch
#define NLB (NB*BLKB)      // 512 loss blocks

// Scratch (__device__ globals per allocation rules)
__device__ unsigned g_bits[NB*NCH*NW];   // bit i of [b][c][j] = (mask(c*32+i, j) != 0)
__device__ float    g_absd[NPIX];        // |dist| = fgd + bgd (one of them is 0)
__device__ float2   g_rowmax[NB*NH];     // per-row (fg_max, bg_max)
__device__ float    g_part[NLB*12];      // per-block partials: [0:4) focal, [4:8) inter, [8:12) (p+t)w

// ---------------------------------------------------------------------------
// Pack mask into per-column bitsets via warp ballot transpose.
// One warp handles a 32x32 tile (rows c*32..c*32+31, cols jg*32..jg*32+31).
__global__ void k_pack(const int* __restrict__ tg) {
    int w    = blockIdx.x * 8 + (threadIdx.x >> 5);  // 512 warps
    int lane = threadIdx.x & 31;
    int b = w >> 6, rem = w & 63, c = rem >> 3, jg = rem & 7;
    int j = jg * 32 + lane;
    const int* base = tg + (b * NH + c * 32) * NW + j;
    unsigned word = 0u;
    #pragma unroll
    for (int i = 0; i < 32; ++i) {
        unsigned bal = __ballot_sync(0xffffffffu, base[i * NW] != 0);
        word |= ((bal >> lane) & 1u) << i;
    }
    g_bits[(b * NCH + c) * NW + j] = word;
}

// Vertical distance to nearest set bit (after XOR with inv) in column jo at row h.
__device__ __forceinline__ float vdist(const unsigned* sw, int jo, int h,
                                       int c0, int b0, unsigned inv) {
    // upward (rows <= h)
    unsigned m = (sw[c0 * NW + jo] ^ inv) & (0xFFFFFFFFu >> (31 - b0));
    int c = c0;
    while (m == 0u && c > 0) m = sw[--c * NW + jo] ^ inv;
    int du = m ? h - (c * 32 + 31 - __clz(m)) : 100000;
    // downward (rows >= h)
    m = (sw[c0 * NW + jo] ^ inv) & (0xFFFFFFFFu << b0);
    c = c0;
    while (m == 0u && c < NCH - 1) m = sw[++c * NW + jo] ^ inv;
    int dd = m ? (c * 32 + __ffs(m) - 1) - h : 100000;
    int d = min(du, dd);
    return (d >= 100000) ? 1e6f : (float)d;
}

// ---------------------------------------------------------------------------
// EDT: vertical dist from bitset + exact pruned horizontal envelope.
// One block per (b, h) row.
__global__ void k_edt() {
    int blk = blockIdx.x;
    int b = blk >> 8, h = blk & 255;
    int jo = threadIdx.x;
    __shared__ unsigned sw[NCH * NW];
    __shared__ float sf[NW], sb[NW];
    #pragma unroll
    for (int c = 0; c < NCH; ++c)
        sw[c * NW + jo] = g_bits[(b * NCH + c) * NW + jo];
    __syncthreads();

    int c0 = h >> 5, b0 = h & 31;
    // fg feature: mask == 0  -> complemented bits; bg feature: mask == 1
    float gf = vdist(sw, jo, h, c0, b0, 0xFFFFFFFFu);
    float gb = vdist(sw, jo, h, c0, b0, 0u);
    sf[jo] = gf;
    sb[jo] = gb;
    __syncthreads();

    float bf = gf * gf;
    float bb = gb * gb;
    for (int r = 1; r < NW; ++r) {
        float c = (float)(r * r);
        if (c >= bf && c >= bb) break;
        int jl = jo - r, jr = jo + r;
        if (jl >= 0) {
            float a = sf[jl], x = sb[jl];
            bf = fminf(bf, a * a + c);
            bb = fminf(bb, x * x + c);
        }
        if (jr < NW) {
            float a = sf[jr], x = sb[jr];
            bf = fminf(bf, a * a + c);
            bb = fminf(bb, x * x + c);
        }
    }
    float fgd = sqrtf(bf);
    float bgd = sqrtf(bb);
    g_absd[(b * NH + h) * NW + jo] = fgd + bgd;

    // deterministic per-row max -> g_rowmax
    float mf = fgd, mb = bgd;
    #pragma unroll
    for (int o = 16; o; o >>= 1) {
        mf = fmaxf(mf, __shfl_down_sync(0xffffffffu, mf, o));
        mb = fmaxf(mb, __shfl_down_sync(0xffffffffu, mb, o));
    }
    __shared__ float smf[8], smb[8];
    int lane = jo & 31, wq = jo >> 5;
    if (lane == 0) { smf[wq] = mf; smb[wq] = mb; }
    __syncthreads();
    if (jo == 0) {
        #pragma unroll
        for (int q = 1; q < 8; ++q) { mf = fmaxf(mf, smf[q]); mb = fmaxf(mb, smb[q]); }
        g_rowmax[blk] = make_float2(mf, mb);
    }
}

// ---------------------------------------------------------------------------
// Fused focal + IoU partials. 64 blocks per batch, 4 pixels per thread (float4).
__global__ void k_loss(const float* __restrict__ p0, const float* __restrict__ p1,
                       const float* __restrict__ p2, const float* __restrict__ p3,
                       const int* __restrict__ tg) {
    int blk = blockIdx.x;
    int b = blk >> 6;
    int tid = threadIdx.x;
    int lane = tid & 31, wq = tid >> 5;

    // batch maxima from per-row maxima (deterministic)
    __shared__ float sA[8], sB[8];
    {
        float2 rm = g_rowmax[b * NH + tid];
        float mf = rm.x, mb = rm.y;
        #pragma unroll
        for (int o = 16; o; o >>= 1) {
            mf = fmaxf(mf, __shfl_down_sync(0xffffffffu, mf, o));
            mb = fmaxf(mb, __shfl_down_sync(0xffffffffu, mb, o));
        }
        if (lane == 0) { sA[wq] = mf; sB[wq] = mb; }
    }
    __syncthreads();
    float mf = sA[0], mb = sB[0];
    #pragma unroll
    for (int q = 1; q < 8; ++q) { mf = fmaxf(mf, sA[q]); mb = fmaxf(mb, sB[q]); }
    float md = fmaxf(mf, mb);
    bool valid = (mb < 9e5f) && (md > 0.f);
    float inv3 = valid ? 3.0f / fmaxf(md, 1e-12f) : 0.f;
    float cfl  = valid ? 1.f : 0.f;

    int pix = b * (NH * NW) + (blk & 63) * 1024 + tid * 4;
    float4 x0 = *(const float4*)(p0 + pix);
    float4 x1 = *(const float4*)(p1 + pix);
    float4 x2 = *(const float4*)(p2 + pix);
    float4 x3 = *(const float4*)(p3 + pix);
    int4   tv = *(const int4*)(tg + pix);
    float4 ad = *(const float4*)(g_absd + pix);

    float X[4][4] = { {x0.x, x1.x, x2.x, x3.x},
                      {x0.y, x1.y, x2.y, x3.y},
                      {x0.z, x1.z, x2.z, x3.z},
                      {x0.w, x1.w, x2.w, x3.w} };
    float T[4]  = { (float)tv.x, (float)tv.y, (float)tv.z, (float)tv.w };
    float AD[4] = { ad.x, ad.y, ad.z, ad.w };

    float acc[12];
    #pragma unroll
    for (int k = 0; k < 12; ++k) acc[k] = 0.f;

    #pragma unroll
    for (int e = 0; e < 4; ++e) {
        float t = T[e];
        float w = 1.f + cfl * __expf(-AD[e] * inv3);
        float tw = t * w;
        float al = (t == 1.f) ? 0.25f : 0.75f;
        float s12 = 1.f - 2.f * t;
        #pragma unroll
        for (int k = 0; k < 4; ++k) {
            float x = X[e][k];
            float y = (t == 1.f) ? -x : x;
            float a = __expf(-fabsf(y));
            float ce = fmaxf(y, 0.f) + __logf(1.f + a);
            float r = __fdividef(1.f, 1.f + a);
            float q = ((y >= 0.f) ? 1.f : a) * r;     // sigmoid(y) = 1 - p_t
            acc[k] += al * q * q * ce;                 // focal
            float p = t + s12 * q;                     // sigmoid(x)
            float pw = p * w;
            acc[4 + k] += pw * t;                      // inter
            acc[8 + k] += pw + tw;                     // (p + t) * w
        }
    }

    #pragma unroll
    for (int k = 0; k < 12; ++k) {
        #pragma unroll
        for (int o = 16; o; o >>= 1)
            acc[k] += __shfl_down_sync(0xffffffffu, acc[k], o);
    }
    __shared__ float sred[8][12];
    if (lane == 0) {
        #pragma unroll
        for (int k = 0; k < 12; ++k) sred[wq][k] = acc[k];
    }
    __syncthreads();
    if (tid < 12) {
        float s = 0.f;
        #pragma unroll
        for (int q = 0; q < 8; ++q) s += sred[q][tid];
        g_part[blk * 12 + tid] = s;
    }
}

// ---------------------------------------------------------------------------
// Final deterministic combine.
__global__ void k_final(float* __restrict__ out) {
    int tid = threadIdx.x;              // 256 threads
    int lane = tid & 31, wq = tid >> 5;

    // IoU: warp wq handles batch wq
    __shared__ float s_iou[NB][4];
    {
        float in_[4] = {0.f,0.f,0.f,0.f}, u_[4] = {0.f,0.f,0.f,0.f};
        for (int r = lane; r < BLKB; r += 32) {
            const float* pp = g_part + (wq * BLKB + r) * 12;
            #pragma unroll
            for (int k = 0; k < 4; ++k) { in_[k] += pp[4 + k]; u_[k] += pp[8 + k]; }
        }
        #pragma unroll
        for (int k = 0; k < 4; ++k) {
            #pragma unroll
            for (int o = 16; o; o >>= 1) {
                in_[k] += __shfl_down_sync(0xffffffffu, in_[k], o);
                u_[k]  += __shfl_down_sync(0xffffffffu, u_[k],  o);
            }
        }
        if (lane == 0) {
            #pragma unroll
            for (int k = 0; k < 4; ++k) {
                float inter = in_[k];
                float un = u_[k] - inter;
                s_iou[wq][k] = (inter + 1e-6f) / (un + 1e-6f);
            }
        }
    }

    // Focal: tree reduce over NLB block-partials
    float f[4] = {0.f,0.f,0.f,0.f};
    for (int i = tid; i < NLB; i += 256) {
        const float* pp = g_part + i * 12;
        #pragma unroll
        for (int k = 0; k < 4; ++k) f[k] += pp[k];
    }
    __shared__ float sf4[4][256];
    #pragma unroll
    for (int k = 0; k < 4; ++k) sf4[k][tid] = f[k];
    __syncthreads();
    for (int s = 128; s; s >>= 1) {
        if (tid < s) {
            #pragma unroll
            for (int k = 0; k < 4; ++k) sf4[k][tid] += sf4[k][tid + s];
        }
        __syncthreads();
    }

    if (tid == 0) {
        const float wgt[4] = { 1.0f, 0.4f, 0.2f, 0.4f / 3.0f };
        float total = 0.f;
        #pragma unroll
        for (int k = 0; k < 4; ++k) {
            float fm = sf4[k][0] / (float)NPIX;
            float is = 0.f;
            #pragma unroll
            for (int b2 = 0; b2 < NB; ++b2) is += s_iou[b2][k];
            float il = 1.f - is / (float)NB;
            total += wgt[k] * (fm + il);
        }
        out[0] = total;
    }
}

extern "C" void kernel_launch(void* const* d_in, const int* in_sizes, int n_in,
                              void* d_out, int out_size) {
    const float* p0 = (const float*)d_in[0];   // pred_main
    const float* p1 = (const float*)d_in[1];   // aux0
    const float* p2 = (const float*)d_in[2];   // aux1
    const float* p3 = (const float*)d_in[3];   // aux2
    const int*   tg = (const int*)d_in[4];     // targets

    k_pack <<<64, 256>>>(tg);
    k_edt  <<<NB * NH, 256>>>();
    k_loss <<<NLB, 256>>>(p0, p1, p2, p3, tg);
    k_final<<<1, 256>>>((float*)d_out);
}